// round 17
// baseline (speedup 1.0000x reference)
#include <cuda_runtime.h>

#define POOL 7
#define FW 128
#define FC 1024
#define CG (FC / 4)          // 256 float4 channel-groups per pixel
#define TPB 128              // 2 groups per thread

__device__ __forceinline__ float4 bilin4(float4 tl, float4 tr, float4 bl, float4 br,
                                         float fx, float fy) {
    float4 o;
    float top, bot;
    top = tl.x + (tr.x - tl.x) * fx;
    bot = bl.x + (br.x - bl.x) * fx;
    o.x = top + (bot - top) * fy;
    top = tl.y + (tr.y - tl.y) * fx;
    bot = bl.y + (br.y - bl.y) * fx;
    o.y = top + (bot - top) * fy;
    top = tl.z + (tr.z - tl.z) * fx;
    bot = bl.z + (br.z - bl.z) * fx;
    o.z = top + (bot - top) * fy;
    top = tl.w + (tr.w - tl.w) * fx;
    bot = bl.w + (br.w - bl.w) * fx;
    o.w = top + (bot - top) * fy;
    return o;
}

__global__ __launch_bounds__(TPB)
void roi_row_bf_kernel(const float* __restrict__ feat,
                       const float* __restrict__ rois,
                       float* __restrict__ out) {
    const int py  = blockIdx.x;           // 0..6
    const int roi = blockIdx.y;           // 0..511

    const float4 r = __ldg(((const float4*)rois) + roi);
    const int ymin = (int)r.x;
    const int xmin = (int)r.y;
    const int ymax = (int)r.z;
    const int xmax = (int)r.w;

    const int ylim = ymax - ymin;
    const int xlim = xmax - xmin;
    const float hs = (float)(ylim + 1) / (float)POOL;
    const float ws = (float)(xlim + 1) / (float)POOL;

    // row geometry (branch-free: dead bottom row redirected to top row)
    const float sy = (float)py * hs;
    const int y0 = (int)floorf(sy);
    const int y1 = min(y0 + 1, ylim);
    const float fy = sy - (float)y0;
    const bool ny = (y1 != y0) && (fy != 0.0f);

    const unsigned row0 = (unsigned)((ymin + y0) * FW + xmin) * CG;
    const unsigned row1 = ny ? (unsigned)((ymin + y1) * FW + xmin) * CG : row0;

    // per-cell column offsets (warp-uniform, branch-free; dead right column
    // redirected to left -> duplicate lines hit L1, never reach LTS)
    unsigned ox0[POOL], ox1[POOL];
    float fxv[POOL];
    #pragma unroll
    for (int px = 0; px < POOL; ++px) {
        const float sx = (float)px * ws;
        const int x0 = (int)floorf(sx);
        const int x1 = min(x0 + 1, xlim);
        const float fx = sx - (float)x0;
        const bool nx = (x1 != x0) && (fx != 0.0f);
        ox0[px] = (unsigned)x0 * CG;
        ox1[px] = nx ? (unsigned)x1 * CG : (unsigned)x0 * CG;
        fxv[px] = fx;
    }

    const float4* __restrict__ featv = (const float4*)feat;
    const unsigned t = threadIdx.x;       // groups t and t+128

    float4* __restrict__ outrow =
        (float4*)(out + ((size_t)roi * (POOL * POOL) + (size_t)py * POOL) * FC) + t;

    // 2-slot software pipeline: 16 independent loads in flight, straight-line SASS
    float4 d[2][8];

    #define LOADCELL(PX, S)                                                   \
        do {                                                                  \
            const unsigned _o00 = row0 + ox0[PX];                             \
            const unsigned _o01 = row0 + ox1[PX];                             \
            const unsigned _o10 = row1 + ox0[PX];                             \
            const unsigned _o11 = row1 + ox1[PX];                             \
            d[S][0] = __ldg(featv + _o00 + t);                                \
            d[S][1] = __ldg(featv + _o00 + t + TPB);                          \
            d[S][2] = __ldg(featv + _o01 + t);                                \
            d[S][3] = __ldg(featv + _o01 + t + TPB);                          \
            d[S][4] = __ldg(featv + _o10 + t);                                \
            d[S][5] = __ldg(featv + _o10 + t + TPB);                          \
            d[S][6] = __ldg(featv + _o11 + t);                                \
            d[S][7] = __ldg(featv + _o11 + t + TPB);                          \
        } while (0)

    LOADCELL(0, 0);
    LOADCELL(1, 1);

    #pragma unroll
    for (int px = 0; px < POOL; ++px) {
        const int s = px & 1;
        const float fx = fxv[px];
        const float4 o0 = bilin4(d[s][0], d[s][2], d[s][4], d[s][6], fx, fy);
        const float4 o1 = bilin4(d[s][1], d[s][3], d[s][5], d[s][7], fx, fy);
        __stcs(outrow + (size_t)px * CG,       o0);
        __stcs(outrow + (size_t)px * CG + TPB, o1);
        if (px + 2 < POOL) LOADCELL(px + 2, s);
    }
    #undef LOADCELL
}

extern "C" void kernel_launch(void* const* d_in, const int* in_sizes, int n_in,
                              void* d_out, int out_size) {
    const float* feat = (const float*)d_in[0];   // (1,128,128,1024) fp32
    const float* rois = (const float*)d_in[1];   // (512,4) fp32
    float* out = (float*)d_out;                  // (512, 7*7*1024) fp32

    dim3 grid(POOL, 512);
    roi_row_bf_kernel<<<grid, TPB>>>(feat, rois, out);
}